// round 10
// baseline (speedup 1.0000x reference)
#include <cuda_runtime.h>
#include <cstdint>

#define NPG 524288           // elements per (b, group)
#define NTOT 33554432        // B*C*H*W

// ---------------- device scratch (static allocation only) ----------------
static __device__ float  d_part[1024 * 2];    // per-block GN partials (sum, sumsq)
static __device__ float  d_weff[8 * 8192];    // [b][k][c*2 + {0=gate,1=upd}]
static __device__ float  d_biaseff[8 * 128];  // [b][c*2 + {0=gate,1=upd}] (interleaved)
static __device__ float  d_gate[NTOT];        // sigmoid(gate logits)
static __device__ float  d_hw[NTOT];          // column-scan result

// ---------------- f32x2 packed FMA helpers --------------------------------
__device__ __forceinline__ unsigned long long fma2(unsigned long long a,
                                                   unsigned long long b,
                                                   unsigned long long c) {
    unsigned long long d;
    asm("fma.rn.f32x2 %0, %1, %2, %3;" : "=l"(d) : "l"(a), "l"(b), "l"(c));
    return d;
}
__device__ __forceinline__ unsigned long long pack2(float lo, float hi) {
    unsigned long long d;
    asm("mov.b64 %0, {%1, %2};" : "=l"(d) : "f"(lo), "f"(hi));
    return d;
}
__device__ __forceinline__ void unpack2(unsigned long long v, float& lo, float& hi) {
    asm("mov.b64 {%0, %1}, %2;" : "=f"(lo), "=f"(hi) : "l"(v));
}
// sigmoid(z) = 0.5*tanh(0.5z) + 0.5 via MUFU.TANH
__device__ __forceinline__ float sigmoid_tanh(float z) {
    float t;
    asm("tanh.approx.f32 %0, %1;" : "=f"(t) : "f"(z * 0.5f));
    return fmaf(0.5f, t, 0.5f);
}

// ---------------- K1: GN partial stats (atomic-free) ---------------------
__global__ __launch_bounds__(256) void k_gn_stats(const float* __restrict__ x) {
    const int grp   = blockIdx.x >> 4;
    const int slice = blockIdx.x & 15;
    const float4* p = (const float4*)x + (size_t)grp * 131072 + slice * 8192;
    float s = 0.f, ss = 0.f;
#pragma unroll 4
    for (int i = threadIdx.x; i < 8192; i += 256) {
        float4 v = p[i];
        s  += (v.x + v.y) + (v.z + v.w);
        ss += (v.x * v.x + v.y * v.y) + (v.z * v.z + v.w * v.w);
    }
    for (int off = 16; off; off >>= 1) {
        s  += __shfl_down_sync(0xffffffffu, s,  off);
        ss += __shfl_down_sync(0xffffffffu, ss, off);
    }
    __shared__ float rs[8], rss[8];
    int w = threadIdx.x >> 5, l = threadIdx.x & 31;
    if (l == 0) { rs[w] = s; rss[w] = ss; }
    __syncthreads();
    if (threadIdx.x == 0) {
        float S = 0.f, SS = 0.f;
#pragma unroll
        for (int i = 0; i < 8; i++) { S += rs[i]; SS += rss[i]; }
        d_part[blockIdx.x * 2 + 0] = S;
        d_part[blockIdx.x * 2 + 1] = SS;
    }
}

// ---------------- K2: finalize stats + fold GN affine into weights -------
// Weights AND bias in interleaved [c*2 + {0=gate,1=upd}] output indexing.
__global__ __launch_bounds__(256) void k_weff(const float* __restrict__ gw,
                                              const float* __restrict__ gb,
                                              const float* __restrict__ uw,
                                              const float* __restrict__ ub,
                                              const float* __restrict__ gnw,
                                              const float* __restrict__ gnb) {
    const int b = blockIdx.x >> 3;
    const int slice = blockIdx.x & 7;
    __shared__ float smu[8], srstd[8];
    if (threadIdx.x < 8) {
        int g = b * 8 + threadIdx.x;
        double S = 0.0, SS = 0.0;
#pragma unroll
        for (int i = 0; i < 16; i++) {
            S  += (double)d_part[(g * 16 + i) * 2 + 0];
            SS += (double)d_part[(g * 16 + i) * 2 + 1];
        }
        const double n = (double)NPG;
        double mu  = S / n;
        double var = SS / n - mu * mu;
        smu[threadIdx.x]   = (float)mu;
        srstd[threadIdx.x] = (float)(1.0 / sqrt(var + 1e-5));
    }
    __syncthreads();
    const int base = slice * 1024;
#pragma unroll 4
    for (int i = 0; i < 4; i++) {
        int idx = base + i * 256 + threadIdx.x;
        int k = idx >> 7, o = idx & 127;
        float w = (o < 64) ? gw[o * 64 + k] : uw[(o - 64) * 64 + k];
        d_weff[b * 8192 + k * 128 + (o & 63) * 2 + (o >> 6)] =
            w * gnw[k] * srstd[k >> 3];
    }
    if (slice == 0 && threadIdx.x < 128) {
        int m = threadIdx.x;           // interleaved output index
        int cc = m >> 1, gu = m & 1;
        float acc = gu ? ub[cc] : gb[cc];
#pragma unroll 8
        for (int k = 0; k < 64; k++) {
            float w = gu ? uw[cc * 64 + k] : gw[cc * 64 + k];
            int g = k >> 3;
            acc += w * (gnb[k] - smu[g] * srstd[g] * gnw[k]);
        }
        d_biaseff[b * 128 + m] = acc;
    }
}

// ---------------- K3: register-tiled GEMM + column scan over W -----------
// Grid 2048 = 8 b x 256 h, 256 threads, 2 CTAs/SM (85KB dynamic smem).
// GEMM: thread tile 8 outputs x 4 px (og = t>>4, pg = t&15), 64 px/iter,
// 4 iters. Per k per warp: 3 LDS.128 (~4 crossbar cyc) -> 16 FFMA2/thread
// (64 fma cyc/warp) -> fma-bound, not crossbar-bound.
// Scan: logits via lsm; thread = (c = t>>2, q = t&3) owns 16 px; width-4
// shfl affine scan (proven R4 structure).
__global__ __launch_bounds__(256, 2) void k_colgemm(const float* __restrict__ x) {
    extern __shared__ float sm[];
    float* wsm = sm;                 // [k][o]        64*128 = 8192 floats
    float* xsm = sm + 8192;          // [k][px,st68]  64*68  = 4352 floats
    float* lsm = sm + 12544;         // [o][px,st68]  128*68 = 8704 floats

    const int t  = threadIdx.x;
    const int b  = blockIdx.x >> 8;
    const int h  = blockIdx.x & 255;
    const int og = t >> 4;           // 0..15: outputs og*8..+7
    const int pg = t & 15;           // 0..15: px pg*4..+3
    const int c  = t >> 2;           // scan channel 0..63
    const int q  = t & 3;            // scan 16-px quarter
    const unsigned FULL = 0xffffffffu;

    // weights -> smem (straight float4 copy; layout pre-interleaved)
    {
        const float4* wsrc = (const float4*)(d_weff + b * 8192);
        float4* wdst = (float4*)wsm;
#pragma unroll
        for (int i = 0; i < 8; i++) wdst[t + i * 256] = wsrc[t + i * 256];
    }
    float biasr[8];
#pragma unroll
    for (int j = 0; j < 8; j++) biasr[j] = d_biaseff[b * 128 + og * 8 + j];

    // X loaders: sl = t + i*256 -> ch = sl>>4, f = sl&15 (float4 within 64px)
    const float* xb = x + (size_t)b * 64 * 65536 + (size_t)h * 256;
    const float* gp[4];
    int so[4];
#pragma unroll
    for (int i = 0; i < 4; i++) {
        int sl = t + i * 256;
        gp[i] = xb + (size_t)(sl >> 4) * 65536 + (sl & 15) * 4;
        so[i] = (sl >> 4) * 68 + (sl & 15) * 4;
    }
    float4 vin[4];
#pragma unroll
    for (int i = 0; i < 4; i++) vin[i] = *(const float4*)gp[i];
#pragma unroll
    for (int i = 0; i < 4; i++) *(float4*)&xsm[so[i]] = vin[i];
#pragma unroll
    for (int i = 0; i < 4; i++) vin[i] = *(const float4*)(gp[i] + 64);
    __syncthreads();                 // X(0) + wsm visible

    float s_prev = 0.f;
    const size_t obase = ((size_t)(b * 64 + c)) * 65536 + (size_t)h * 256;

#pragma unroll 1
    for (int it = 0; it < 4; it++) {
        // ---- GEMM: logits = W @ X + bias ----
        unsigned long long acc[8][2];
#pragma unroll
        for (int j = 0; j < 8; j++) {
            unsigned long long bb = pack2(biasr[j], biasr[j]);
            acc[j][0] = bb; acc[j][1] = bb;
        }
#pragma unroll 8
        for (int k = 0; k < 64; k++) {
            float w[8];
            *(float4*)&w[0] = *(const float4*)&wsm[k * 128 + og * 8];
            *(float4*)&w[4] = *(const float4*)&wsm[k * 128 + og * 8 + 4];
            ulonglong2 xp = *(const ulonglong2*)&xsm[k * 68 + pg * 4];
#pragma unroll
            for (int j = 0; j < 8; j++) {
                unsigned long long w2 = pack2(w[j], w[j]);
                acc[j][0] = fma2(w2, xp.x, acc[j][0]);
                acc[j][1] = fma2(w2, xp.y, acc[j][1]);
            }
        }
        // ---- logits -> lsm ----
#pragma unroll
        for (int j = 0; j < 8; j++) {
            float4 v;
            unpack2(acc[j][0], v.x, v.y);
            unpack2(acc[j][1], v.z, v.w);
            *(float4*)&lsm[(og * 8 + j) * 68 + pg * 4] = v;
        }
        __syncthreads();             // L visible; GEMM done with xsm

        // stage next X / prefetch next-next (overlaps scan)
        if (it < 3) {
#pragma unroll
            for (int i = 0; i < 4; i++) *(float4*)&xsm[so[i]] = vin[i];
        }
        if (it < 2) {
#pragma unroll
            for (int i = 0; i < 4; i++)
                vin[i] = *(const float4*)(gp[i] + (it + 2) * 64);
        }

        // ---- scan: thread owns channel c, px quarter q (16 px) ----
        float gv[16], uv[16];
        {
            const float* lg = &lsm[(2 * c) * 68 + q * 16];
            const float* lu = &lsm[(2 * c + 1) * 68 + q * 16];
#pragma unroll
            for (int j4 = 0; j4 < 4; j4++) {
                float4 a = *(const float4*)(lg + j4 * 4);
                float4 d = *(const float4*)(lu + j4 * 4);
                gv[j4*4+0] = a.x; gv[j4*4+1] = a.y; gv[j4*4+2] = a.z; gv[j4*4+3] = a.w;
                uv[j4*4+0] = d.x; uv[j4*4+1] = d.y; uv[j4*4+2] = d.z; uv[j4*4+3] = d.w;
            }
        }
#pragma unroll
        for (int j = 0; j < 16; j++) {
            gv[j] = sigmoid_tanh(gv[j]);
            uv[j] = fmaf(-gv[j], uv[j], uv[j]);   // (1-g)*u
        }
        // composite over own 16 px
        float Ac = 1.f, Bc = 0.f;
#pragma unroll
        for (int j = 0; j < 16; j++) {
            Ac = Ac * gv[j];
            Bc = fmaf(gv[j], Bc, uv[j]);
        }
        // width-4 inclusive Hillis-Steele over q lanes
        float Ai = Ac, Bi = Bc;
        {
            float Au = __shfl_up_sync(FULL, Ai, 1, 4);
            float Bu = __shfl_up_sync(FULL, Bi, 1, 4);
            if (q >= 1) { Bi = fmaf(Ai, Bu, Bi); Ai *= Au; }
            Au = __shfl_up_sync(FULL, Ai, 2, 4);
            Bu = __shfl_up_sync(FULL, Bi, 2, 4);
            if (q >= 2) { Bi = fmaf(Ai, Bu, Bi); Ai *= Au; }
        }
        float Ax = __shfl_up_sync(FULL, Ai, 1, 4);
        float Bx = __shfl_up_sync(FULL, Bi, 1, 4);
        float sin0 = (q == 0) ? s_prev : fmaf(Ax, s_prev, Bx);
        float A3 = __shfl_sync(FULL, Ai, 3, 4);
        float B3 = __shfl_sync(FULL, Bi, 3, 4);
        s_prev = fmaf(A3, s_prev, B3);

        // sequential re-apply + writeback
        float* gout = d_gate + obase + it * 64 + q * 16;
        float* hout = d_hw   + obase + it * 64 + q * 16;
        float s = sin0;
#pragma unroll
        for (int j4 = 0; j4 < 4; j4++) {
            float4 sv;
            s = fmaf(gv[j4*4+0], s, uv[j4*4+0]); sv.x = s;
            s = fmaf(gv[j4*4+1], s, uv[j4*4+1]); sv.y = s;
            s = fmaf(gv[j4*4+2], s, uv[j4*4+2]); sv.z = s;
            s = fmaf(gv[j4*4+3], s, uv[j4*4+3]); sv.w = s;
            *(float4*)(gout + j4 * 4) =
                make_float4(gv[j4*4], gv[j4*4+1], gv[j4*4+2], gv[j4*4+3]);
            *(float4*)(hout + j4 * 4) = sv;
        }
        __syncthreads();             // X(it+1) visible; lsm free
    }
}

// ---------------- K4: row scan over H + residual add ---------------------
__global__ __launch_bounds__(128) void k_rowscan(const float* __restrict__ x,
                                                 float* __restrict__ out) {
    const int idx  = blockIdx.x * 128 + threadIdx.x;     // 0..131071
    const int base = (idx >> 8) * 65536 + (idx & 255);   // (b*64+c)*HW + w
    float s = 0.f;
#pragma unroll 1
    for (int h = 0; h < 256; h += 8) {
        const int r = base + (h << 8);
        float g[8], u[8], xv[8];
#pragma unroll
        for (int j = 0; j < 8; j++) g[j] = d_gate[r + (j << 8)];
#pragma unroll
        for (int j = 0; j < 8; j++) u[j] = d_hw[r + (j << 8)];
#pragma unroll
        for (int j = 0; j < 8; j++) xv[j] = __ldcs(&x[r + (j << 8)]);
#pragma unroll
        for (int j = 0; j < 8; j++) {
            s = fmaf(g[j], s, fmaf(-g[j], u[j], u[j]));
            __stcs(&out[r + (j << 8)], xv[j] + s);
        }
    }
}

// ---------------- launch --------------------------------------------------
#define COLGEMM_SMEM (21248 * 4)   // 84,992 bytes

extern "C" void kernel_launch(void* const* d_in, const int* in_sizes, int n_in,
                              void* d_out, int out_size) {
    const float* x      = (const float*)d_in[0];
    const float* gn_w   = (const float*)d_in[1];
    const float* gn_b   = (const float*)d_in[2];
    const float* gate_w = (const float*)d_in[3];
    const float* gate_b = (const float*)d_in[4];
    const float* upd_w  = (const float*)d_in[5];
    const float* upd_b  = (const float*)d_in[6];
    float* out = (float*)d_out;

    cudaFuncSetAttribute(k_colgemm,
                         cudaFuncAttributeMaxDynamicSharedMemorySize,
                         COLGEMM_SMEM);

    k_gn_stats<<<1024, 256>>>(x);
    k_weff<<<64, 256>>>(gate_w, gate_b, upd_w, upd_b, gn_w, gn_b);
    k_colgemm<<<2048, 256, COLGEMM_SMEM>>>(x);
    k_rowscan<<<1024, 128>>>(x, out);
}